// round 16
// baseline (speedup 1.0000x reference)
#include <cuda_runtime.h>
#include <cuda_bf16.h>
#include <cuda_fp16.h>
#include <math.h>
#include <stdint.h>

#define Bq 8
#define Cq 256
#define Hq 128
#define Wq 128
#define Pq (Hq*Wq)
#define NHq 8
#define HDq 32
#define NGq (Bq*NHq)

// Scratch (no allocations allowed)
__device__ float g_ix[Bq*NHq*Pq];
__device__ float g_iy[Bq*NHq*Pq];
// V as half2-per-2ch (B,NH,P,HD/2) u32; reused as fp16 pre-norm (B,C,P) halves
__device__ uint32_t g_Vp[(size_t)Bq*Cq*Pq/2];
__device__ __half g_xT[(size_t)Bq*Pq*Cq];          // x transposed (B,P,C) fp16
__device__ __half g_ST[(size_t)Bq*Pq*Cq];          // sampled (B,P,C) fp16
__device__ __half g_wv[Cq*Cq];                     // weights fp16
__device__ __half g_wo[Cq*Cq];
__device__ float g_sum[NGq];
__device__ float g_sq [NGq];
__device__ float g_mean[NGq];
__device__ float g_rstd[NGq];

// ---------------------------------------------------------------- helpers
__device__ __forceinline__ uint32_t smem_u32(const void* p) {
    uint32_t a;
    asm("{ .reg .u64 t; cvta.to.shared.u64 t, %1; cvt.u32.u64 %0, t; }" : "=r"(a) : "l"(p));
    return a;
}

__device__ __forceinline__ uint32_t swz(uint32_t byte) {
    return byte ^ ((byte >> 3) & 0x70);
}

__device__ __forceinline__ void ldsm4(uint32_t* r, uint32_t a) {
    asm volatile("ldmatrix.sync.aligned.m8n8.x4.shared.b16 {%0,%1,%2,%3}, [%4];"
        : "=r"(r[0]), "=r"(r[1]), "=r"(r[2]), "=r"(r[3]) : "r"(a));
}

// fp16 MMA, fp32 accumulate
__device__ __forceinline__ void mma16816(float* d, const uint32_t* a, const uint32_t* b) {
    asm volatile(
        "mma.sync.aligned.m16n8k16.row.col.f32.f16.f16.f32 "
        "{%0,%1,%2,%3}, {%4,%5,%6,%7}, {%8,%9}, {%0,%1,%2,%3};"
        : "+f"(d[0]), "+f"(d[1]), "+f"(d[2]), "+f"(d[3])
        : "r"(a[0]), "r"(a[1]), "r"(a[2]), "r"(a[3]), "r"(b[0]), "r"(b[1]));
}

__device__ __forceinline__ uint32_t a_addr(uint32_t base, int m_base, int cb, int lane) {
    int mat = lane >> 3, r = lane & 7;
    int row = m_base + ((mat & 1) << 3) + r;
    return base + swz((uint32_t)(row * 128 + cb + ((mat >> 1) << 4)));
}

__device__ __forceinline__ uint32_t b_addr(uint32_t base, int n_base, int cb, int lane) {
    int mat = lane >> 3, r = lane & 7;
    int row = n_base + ((mat >> 1) << 3) + r;
    return base + swz((uint32_t)(row * 128 + cb + ((mat & 1) << 4)));
}

__device__ __forceinline__ void cp16(uint32_t s, const void* g) {
    asm volatile("cp.async.cg.shared.global [%0], [%1], 16;" :: "r"(s), "l"(g));
}

__device__ __forceinline__ uint32_t pack2h(float a, float b) {
    __half2 h = __floats2half2_rn(a, b);
    return *(uint32_t*)&h;
}
__device__ __forceinline__ float2 up2h(uint32_t u) {
    __half2 h = *(__half2*)&u;
    return __half22float2(h);
}

// ---------------------------------------------------------------- small kernels
__global__ void k_wcvt(const float* __restrict__ vw, const float* __restrict__ ow) {
    int tid = threadIdx.x;
    if (blockIdx.x == 0 && tid < NGq) { g_sum[tid] = 0.f; g_sq[tid] = 0.f; }
    int idx = blockIdx.x * 256 + tid;
    int e = idx * 2;
    ((uint32_t*)g_wv)[idx] = pack2h(__ldg(vw + e), __ldg(vw + e + 1));
    ((uint32_t*)g_wo)[idx] = pack2h(__ldg(ow + e), __ldg(ow + e + 1));
}

// x (B,C,P) fp32 -> g_xT (B,P,C) fp16
__global__ void __launch_bounds__(256) k_cvt(const float* __restrict__ x) {
    __shared__ float xs[32][65];
    const int tid = threadIdx.x;
    const int p0 = blockIdx.x * 32, c0 = blockIdx.y * 64, b = blockIdx.z;
    const float* xb = x + (size_t)b * Cq * Pq;
#pragma unroll
    for (int i = 0; i < 8; i++) {
        int idx = tid + i * 256;
        int cr = idx >> 5, pc = idx & 31;
        xs[pc][cr] = xb[(size_t)(c0 + cr) * Pq + p0 + pc];
    }
    __syncthreads();
    uint32_t* dst = (uint32_t*)g_xT;
#pragma unroll
    for (int i = 0; i < 4; i++) {
        int idx = tid + i * 256;
        int pr = idx >> 5, c2 = (idx & 31) * 2;
        size_t e = (size_t)b * Pq * Cq + (size_t)(p0 + pr) * Cq + c0 + c2;
        dst[e >> 1] = pack2h(xs[pr][c2], xs[pr][c2 + 1]);
    }
}

// Fused dwconv 3x3 -> offset proj -> tanh -> grid coords.
// 8 channels per group, double-buffered cp.async; dynamic smem (58368 B).
#define OFFS_SMEM (32768 + 16384 + 9216)
__global__ void __launch_bounds__(256) k_offsets(const float* __restrict__ x,
                                                 const float* __restrict__ dw,
                                                 const float* __restrict__ offw,
                                                 const float* __restrict__ offb) {
    extern __shared__ char dsm[];
    float* xs     = (float*)dsm;              // [2][8][4][128] = 32768 B
    float* offw_s = (float*)(dsm + 32768);    // [256][16]      = 16384 B
    float* dw_s   = (float*)(dsm + 49152);    // [256*9]        =  9216 B

    const int tid = threadIdx.x;
    const int px  = tid & 127;
    const int ry  = tid >> 7;
    const int b   = blockIdx.y;
    const int r0  = blockIdx.x * 2;

    for (int i = tid; i < Cq*9; i += 256) dw_s[i] = __ldg(dw + i);
#pragma unroll
    for (int o = 0; o < 16; o++) offw_s[tid*16 + o] = __ldg(offw + o*Cq + tid);

    float acc[16];
#pragma unroll
    for (int o = 0; o < 16; o++) acc[o] = __ldg(offb + o);

    const float* xb = x + (size_t)b * Cq * Pq;

    // xs element offset: ((buf*8 + ci)*4 + rr)*128 + px
    auto prefetch = [&](int g, int buf) {
        int c0 = g * 8;
#pragma unroll
        for (int i = 0; i < 4; i++) {
            int idx = tid + i * 256;                 // 0..1023
            int ci = idx >> 7;                       // 0..7
            int rr = (idx >> 5) & 3;                 // 0..3
            int p4 = (idx & 31) * 4;
            int gr = r0 - 1 + rr;
            float* dstp = xs + (((buf*8 + ci)*4 + rr) << 7) + p4;
            if (gr >= 0 && gr < Hq) {
                cp16(smem_u32(dstp), xb + (size_t)(c0 + ci) * Pq + gr * Wq + p4);
            } else {
                *(float4*)dstp = make_float4(0.f, 0.f, 0.f, 0.f);
            }
        }
    };

    prefetch(0, 0);
    asm volatile("cp.async.commit_group;");

    for (int g = 0; g < 32; g++) {
        if (g < 31) {
            prefetch(g + 1, (g + 1) & 1);
            asm volatile("cp.async.commit_group;");
            asm volatile("cp.async.wait_group 1;");
        } else {
            asm volatile("cp.async.wait_group 0;");
        }
        __syncthreads();
        const int buf = g & 1;
        const int c0  = g * 8;
#pragma unroll
        for (int ci = 0; ci < 8; ci++) {
            const int c = c0 + ci;
            const float* wv = &dw_s[c*9];
            const float* base = xs + (((buf*8 + ci)*4) << 7);
            float hv = 0.f;
#pragma unroll
            for (int ky = 0; ky < 3; ky++) {
                const float* row = base + ((ry + ky) << 7);
                if (px > 0)      hv = fmaf(row[px-1], wv[ky*3+0], hv);
                                 hv = fmaf(row[px  ], wv[ky*3+1], hv);
                if (px < Wq-1)   hv = fmaf(row[px+1], wv[ky*3+2], hv);
            }
#pragma unroll
            for (int o4 = 0; o4 < 4; o4++) {
                float4 w4 = *(const float4*)&offw_s[c*16 + o4*4];
                acc[o4*4+0] = fmaf(hv, w4.x, acc[o4*4+0]);
                acc[o4*4+1] = fmaf(hv, w4.y, acc[o4*4+1]);
                acc[o4*4+2] = fmaf(hv, w4.z, acc[o4*4+2]);
                acc[o4*4+3] = fmaf(hv, w4.w, acc[o4*4+3]);
            }
        }
        __syncthreads();
    }

    const int y = r0 + ry;
    const int p = y * Wq + px;
    float gy = -1.f + 2.f * (float)y  / (float)(Hq - 1);
    float gx = -1.f + 2.f * (float)px / (float)(Wq - 1);
#pragma unroll
    for (int hh = 0; hh < NHq; hh++) {
        float dy = tanhf(acc[2*hh  ]) * 0.5f;
        float dx = tanhf(acc[2*hh+1]) * 0.5f;
        float sy = fminf(fmaxf(gy + dy, -1.f), 1.f);
        float sx = fminf(fmaxf(gx + dx, -1.f), 1.f);
        g_iy[(b*NHq + hh)*Pq + p] = (sy + 1.f) * 0.5f * (float)(Hq - 1);
        g_ix[(b*NHq + hh)*Pq + p] = (sx + 1.f) * 0.5f * (float)(Wq - 1);
    }
}

// Bilinear sampling from fp16 V (B,NH,P,HD/2 u32) -> g_ST (B,P,C) fp16
__global__ void __launch_bounds__(256) k_sample() {
    const int tid = threadIdx.x;
    const int p0  = blockIdx.x * 256;
    const int hh  = blockIdx.y;
    const int b   = blockIdx.z;
    const int p   = p0 + tid;
    const int bh  = b * NHq + hh;

    float ixv = g_ix[bh*Pq + p];
    float iyv = g_iy[bh*Pq + p];
    float x0f = floorf(ixv), y0f = floorf(iyv);
    float wx = ixv - x0f, wy = iyv - y0f;
    int x0 = min(max((int)x0f,     0), Wq - 1);
    int x1 = min(max((int)x0f + 1, 0), Wq - 1);
    int y0 = min(max((int)y0f,     0), Hq - 1);
    int y1 = min(max((int)y0f + 1, 0), Hq - 1);
    float w00 = (1.f-wx)*(1.f-wy), w01 = wx*(1.f-wy);
    float w10 = (1.f-wx)*wy,       w11 = wx*wy;

    const int HD2 = HDq / 2;
    const uint32_t* V00 = g_Vp + ((size_t)bh * Pq + (y0*Wq + x0)) * HD2;
    const uint32_t* V01 = g_Vp + ((size_t)bh * Pq + (y0*Wq + x1)) * HD2;
    const uint32_t* V10 = g_Vp + ((size_t)bh * Pq + (y1*Wq + x0)) * HD2;
    const uint32_t* V11 = g_Vp + ((size_t)bh * Pq + (y1*Wq + x1)) * HD2;

    size_t e = (size_t)b * Pq * Cq + (size_t)p * Cq + hh * HDq;
    uint32_t* dst = (uint32_t*)g_ST + (e >> 1);

#pragma unroll
    for (int ch = 0; ch < 4; ch++) {
        uint4 a = *(const uint4*)(V00 + ch*4);
        uint4 bb= *(const uint4*)(V01 + ch*4);
        uint4 c = *(const uint4*)(V10 + ch*4);
        uint4 d = *(const uint4*)(V11 + ch*4);
        uint32_t ua[4] = {a.x,a.y,a.z,a.w};
        uint32_t ub[4] = {bb.x,bb.y,bb.z,bb.w};
        uint32_t uc[4] = {c.x,c.y,c.z,c.w};
        uint32_t ud[4] = {d.x,d.y,d.z,d.w};
        uint32_t o[4];
#pragma unroll
        for (int j = 0; j < 4; j++) {
            float2 fa = up2h(ua[j]), fb = up2h(ub[j]);
            float2 fc = up2h(uc[j]), fd = up2h(ud[j]);
            float vx = w00*fa.x + w01*fb.x + w10*fc.x + w11*fd.x;
            float vy = w00*fa.y + w01*fb.y + w10*fc.y + w11*fd.y;
            o[j] = pack2h(vx, vy);
        }
        *(uint4*)(dst + ch*4) = make_uint4(o[0], o[1], o[2], o[3]);
    }
}

__global__ void k_finalize() {
    int g = threadIdx.x;
    if (g < NGq) {
        float n  = (float)(HDq * Pq);
        float mu = g_sum[g] / n;
        float var = g_sq[g] / n - mu * mu;
        g_mean[g] = mu;
        g_rstd[g] = rsqrtf(var + 1e-5f);
    }
}

// out = x + (pre - mean)*rstd*gamma + beta; pre read as fp16 halves from g_Vp
__global__ void k_norm(const float* __restrict__ x,
                       const float* __restrict__ gamma,
                       const float* __restrict__ beta,
                       float* __restrict__ out) {
    size_t i = ((size_t)blockIdx.x * blockDim.x + threadIdx.x) * 4;
    int c = (int)((i / Pq) % Cq);
    int b = (int)(i / ((size_t)Cq * Pq));
    int g = b * NHq + c / HDq;
    float mu = g_mean[g], rs = g_rstd[g];
    float gm = __ldg(gamma + c), bt = __ldg(beta + c);
    uint2 pv = *(const uint2*)(g_Vp + (i >> 1));
    float2 v01 = up2h(pv.x), v23 = up2h(pv.y);
    float4 xv = *(const float4*)(x + i);
    float4 o;
    o.x = xv.x + (v01.x - mu) * rs * gm + bt;
    o.y = xv.y + (v01.y - mu) * rs * gm + bt;
    o.z = xv.z + (v23.x - mu) * rs * gm + bt;
    o.w = xv.w + (v23.y - mu) * rs * gm + bt;
    *(float4*)(out + i) = o;
}

// ---------------------------------------------------------------- pipelined HMMA GEMM (fp16, single pass)
#define STAGE_BYTES 32768
#define NSTAGE 2
#define SMEM_GEMM_BYTES (STAGE_BYTES*NSTAGE + 64)

template<bool STATS, bool PACKV>
__global__ void __launch_bounds__(256, 2) k_gemm_pipe(
    const __half* __restrict__ A,
    const __half* __restrict__ B,
    uint32_t* __restrict__ OutP) {
    extern __shared__ char dsm[];
    const int tid   = threadIdx.x;
    const int lane  = tid & 31;
    const int wid   = tid >> 5;
    const int b     = blockIdx.z;
    const int om    = blockIdx.y * 128;
    const int p0    = blockIdx.x * 128;
    const int mwarp = wid & 1;
    const int nwarp = wid >> 1;

    uint32_t sb = smem_u32(dsm);
    float* ssum = (float*)(dsm + STAGE_BYTES*NSTAGE);
    if (STATS && tid < 8) ssum[tid] = 0.f;

    const __half* Bb = B + (size_t)b * Pq * Cq;

    float acc[4][4][4] = {};

    auto prefetch = [&](int kc, int st) {
        uint32_t s0 = sb + st * STAGE_BYTES;
        const int kofs = kc * 64;
#pragma unroll
        for (int i = 0; i < 8; i++) {
            int idx = tid + i * 256;
            int t   = idx >> 10;
            int r   = (idx >> 3) & 127;
            int ch  = idx & 7;
            uint32_t dst = s0 + t * 16384 + swz((uint32_t)(r * 128 + ch * 16));
            const __half* src = t == 0
                ? A  + (size_t)(om + r) * Cq + kofs + ch * 8
                : Bb + (size_t)(p0 + r) * Cq + kofs + ch * 8;
            cp16(dst, src);
        }
    };

    prefetch(0, 0);
    asm volatile("cp.async.commit_group;");

    for (int kc = 0; kc < 4; kc++) {
        asm volatile("cp.async.wait_group 0;");
        __syncthreads();
        if (kc + 1 < 4) {
            prefetch(kc + 1, (kc + 1) & 1);
            asm volatile("cp.async.commit_group;");
        }

        const uint32_t sA = sb + (kc & 1) * STAGE_BYTES;
        const uint32_t sB = sA + 16384;

#pragma unroll
        for (int ks = 0; ks < 4; ks++) {
            const int cb = ks * 32;
            uint32_t bf[8];
#pragma unroll
            for (int t2 = 0; t2 < 2; t2++)
                ldsm4(&bf[t2 * 4], b_addr(sB, nwarp * 32 + t2 * 16, cb, lane));
#pragma unroll
            for (int mt = 0; mt < 4; mt++) {
                uint32_t af[4];
                ldsm4(af, a_addr(sA, mwarp * 64 + mt * 16, cb, lane));
#pragma unroll
                for (int nt = 0; nt < 4; nt++)
                    mma16816(acc[mt][nt], af, &bf[nt * 2]);
            }
        }
    }
    __syncthreads();

    const int g  = lane >> 2;
    const int s2 = (lane & 3) * 2;

    if (PACKV) {
        __half (*stageh)[138] = (__half (*)[138])dsm;
#pragma unroll
        for (int mt = 0; mt < 4; mt++) {
            int row = mwarp * 64 + mt * 16 + g;
#pragma unroll
            for (int nt = 0; nt < 4; nt++) {
                int col = nwarp * 32 + nt * 8 + s2;
                stageh[row    ][col  ] = __float2half_rn(acc[mt][nt][0]);
                stageh[row    ][col+1] = __float2half_rn(acc[mt][nt][1]);
                stageh[row + 8][col  ] = __float2half_rn(acc[mt][nt][2]);
                stageh[row + 8][col+1] = __float2half_rn(acc[mt][nt][3]);
            }
        }
        __syncthreads();
        const int HD2 = HDq / 2;
        const int head_l = wid & 3;
        const int p_half = (wid >> 2) * 64;
        const int cl   = lane & 15;
        const int pofs = lane >> 4;
        uint32_t* Vp = OutP + ((size_t)(b*NHq + (om >> 5) + head_l) * Pq + p0 + p_half) * HD2;
#pragma unroll 4
        for (int pp = 0; pp < 64; pp += 2) {
            int col = p_half + pp + pofs;
            __half h0 = stageh[head_l*32 + 2*cl    ][col];
            __half h1 = stageh[head_l*32 + 2*cl + 1][col];
            uint32_t u = (uint32_t)__half_as_ushort(h0) | ((uint32_t)__half_as_ushort(h1) << 16);
            Vp[(size_t)(pp + pofs) * HD2 + cl] = u;
        }
        return;
    }

    __half* Ob = (__half*)OutP + (size_t)b * Cq * Pq;
    float slocal[2] = {0.f, 0.f}, qlocal[2] = {0.f, 0.f};
#pragma unroll
    for (int mt = 0; mt < 4; mt++) {
        int o0 = om + mwarp * 64 + mt * 16 + g;
#pragma unroll
        for (int nt = 0; nt < 4; nt++) {
            int p = p0 + nwarp * 32 + nt * 8 + s2;
            float d0 = acc[mt][nt][0], d1 = acc[mt][nt][1];
            float d2 = acc[mt][nt][2], d3 = acc[mt][nt][3];
            *(uint32_t*)(Ob + (size_t)o0 * Pq + p)       = pack2h(d0, d1);
            *(uint32_t*)(Ob + (size_t)(o0 + 8) * Pq + p) = pack2h(d2, d3);
            if (STATS) {
                int j = mt >> 1;
                slocal[j] += d0 + d1 + d2 + d3;
                qlocal[j] += d0*d0 + d1*d1 + d2*d2 + d3*d3;
            }
        }
    }

    if (STATS) {
#pragma unroll
        for (int j = 0; j < 2; j++) {
#pragma unroll
            for (int o = 16; o; o >>= 1) {
                slocal[j] += __shfl_xor_sync(0xFFFFFFFFu, slocal[j], o);
                qlocal[j] += __shfl_xor_sync(0xFFFFFFFFu, qlocal[j], o);
            }
            if (lane == 0) {
                int gidx = mwarp * 2 + j;
                atomicAdd(&ssum[gidx],     slocal[j]);
                atomicAdd(&ssum[4 + gidx], qlocal[j]);
            }
        }
        __syncthreads();
        if (tid < 4) {
            int gg = b * NHq + blockIdx.y * 4 + tid;
            atomicAdd(&g_sum[gg], ssum[tid]);
            atomicAdd(&g_sq[gg],  ssum[4 + tid]);
        }
    }
}

// ---------------------------------------------------------------- launch
extern "C" void kernel_launch(void* const* d_in, const int* in_sizes, int n_in,
                              void* d_out, int out_size) {
    const float* x     = (const float*)d_in[0];
    const float* dw    = (const float*)d_in[1];
    const float* offw  = (const float*)d_in[2];
    const float* offb  = (const float*)d_in[3];
    const float* vw    = (const float*)d_in[4];
    const float* ow    = (const float*)d_in[5];
    const float* gamma = (const float*)d_in[6];
    const float* beta  = (const float*)d_in[7];
    float* out = (float*)d_out;

    static cudaStream_t s_side = nullptr;
    static cudaEvent_t  ev_fork = nullptr, ev_join = nullptr;
    if (!s_side) {
        cudaStreamCreateWithFlags(&s_side, cudaStreamNonBlocking);
        cudaEventCreateWithFlags(&ev_fork, cudaEventDisableTiming);
        cudaEventCreateWithFlags(&ev_join, cudaEventDisableTiming);
        cudaFuncSetAttribute(k_gemm_pipe<false,true>, cudaFuncAttributeMaxDynamicSharedMemorySize, SMEM_GEMM_BYTES);
        cudaFuncSetAttribute(k_gemm_pipe<true,false>, cudaFuncAttributeMaxDynamicSharedMemorySize, SMEM_GEMM_BYTES);
        cudaFuncSetAttribute(k_offsets, cudaFuncAttributeMaxDynamicSharedMemorySize, OFFS_SMEM);
    }

    uint32_t* gVp = nullptr;
    cudaGetSymbolAddress((void**)&gVp, g_Vp);
    __half *xT, *ST, *wv, *wo;
    cudaGetSymbolAddress((void**)&xT, g_xT);
    cudaGetSymbolAddress((void**)&ST, g_ST);
    cudaGetSymbolAddress((void**)&wv, g_wv);
    cudaGetSymbolAddress((void**)&wo, g_wo);

    // Fork: k_offsets on side stream, overlapped with cvt + gemm1
    cudaEventRecord(ev_fork, 0);
    cudaStreamWaitEvent(s_side, ev_fork, 0);
    k_offsets<<<dim3(Hq/2, Bq), 256, OFFS_SMEM, s_side>>>(x, dw, offw, offb);
    cudaEventRecord(ev_join, s_side);

    // Main chain
    k_wcvt<<<128, 256>>>(vw, ow);
    k_cvt<<<dim3(Pq/32, Cq/64, Bq), 256>>>(x);
    // V projection -> fp16 packed (B,NH,P,HD/2) in g_Vp
    k_gemm_pipe<false,true><<<dim3(Pq/128, Cq/128, Bq), 256, SMEM_GEMM_BYTES>>>(wv, xT, gVp);

    // Join: sampling needs both offsets and V
    cudaStreamWaitEvent(0, ev_join, 0);
    k_sample<<<dim3(Pq/256, NHq, Bq), 256>>>();
    // O projection -> fp16 pre-norm into g_Vp (V no longer needed) + stats
    k_gemm_pipe<true,false><<<dim3(Pq/128, Cq/128, Bq), 256, SMEM_GEMM_BYTES>>>(wo, ST, gVp);
    k_finalize<<<1, 64>>>();
    k_norm<<<(Bq*Cq*Pq)/1024, 256>>>(x, gamma, beta, out);
}